// round 15
// baseline (speedup 1.0000x reference)
#include <cuda_runtime.h>
#include <cuda_bf16.h>
#include <math.h>
#include <stdint.h>

#define N_NODES 100000
#define N_EDGES 1600000
#define N_GRAPHS 1024
#define D 128
#define NCHUNK ((N_NODES + 1023) / 1024)   // 98

// ---------------------------------------------------------------------------
// Scratch (allocation-free: __device__ globals)
// ---------------------------------------------------------------------------
__device__ uint8_t g_hs[(size_t)N_NODES * D];          // 12.8 MB (hs as e4m3)
__device__ __nv_bfloat16 g_actb[(size_t)N_NODES * D];  // 25.6 MB (act1, bf16)
__device__ __nv_bfloat16 g_xb[(size_t)N_NODES * D];    // 25.6 MB (x as bf16)
__device__ float g_dis[N_NODES];
__device__ float g_pool[N_GRAPHS * D];
__device__ float g_cnt[N_GRAPHS];
__device__ int   g_deg[N_NODES];
__device__ int   g_off[N_NODES];    // chunk-local exclusive offsets
__device__ int   g_cur[N_NODES];    // fill cursors (zeroed each launch)
__device__ int   g_sums[256];       // per-chunk totals
__device__ int   g_csr[N_EDGES];

// ---------------------------------------------------------------------------
// Helpers
// ---------------------------------------------------------------------------
__device__ __forceinline__ uint32_t pack2(float lo, float hi) {
    __nv_bfloat162 h = __float22bfloat162_rn(make_float2(lo, hi));
    return *reinterpret_cast<uint32_t*>(&h);
}

__device__ __forceinline__ unsigned short pack_fp8x2(float lo, float hi) {
    unsigned short r;
    asm("cvt.rn.satfinite.e4m3x2.f32 %0, %1, %2;" : "=h"(r) : "f"(hi), "f"(lo));
    return r;
}

__device__ __forceinline__ float4 fp8x4_to_float4(uint32_t v) {
    uint32_t h01, h23;
    asm("cvt.rn.f16x2.e4m3x2 %0, %1;" : "=r"(h01) : "h"((unsigned short)(v & 0xffffu)));
    asm("cvt.rn.f16x2.e4m3x2 %0, %1;" : "=r"(h23) : "h"((unsigned short)(v >> 16)));
    float2 f01 = __half22float2(*reinterpret_cast<__half2*>(&h01));
    float2 f23 = __half22float2(*reinterpret_cast<__half2*>(&h23));
    return make_float4(f01.x, f01.y, f23.x, f23.y);
}

__device__ __forceinline__ float4 ld_row_fp8(const uint8_t* base, int lane) {
    uint32_t r = __ldg((const uint32_t*)base + lane);
    return fp8x4_to_float4(r);
}

__device__ __forceinline__ uint32_t s2u(const void* p) {
    return (uint32_t)__cvta_generic_to_shared(p);
}

__device__ __forceinline__ void cpa16(uint32_t dst, const void* src, bool v) {
    int sz = v ? 16 : 0;
    asm volatile("cp.async.cg.shared.global [%0], [%1], 16, %2;"
                 :: "r"(dst), "l"(src), "r"(sz));
}

__device__ __forceinline__ void ldsm_x4(uint32_t* r, uint32_t addr) {
    asm volatile("ldmatrix.sync.aligned.m8n8.x4.shared.b16 {%0,%1,%2,%3}, [%4];"
                 : "=r"(r[0]), "=r"(r[1]), "=r"(r[2]), "=r"(r[3]) : "r"(addr));
}

__device__ __forceinline__ void ldsm_x4_t(uint32_t* r, uint32_t addr) {
    asm volatile("ldmatrix.sync.aligned.m8n8.x4.trans.shared.b16 {%0,%1,%2,%3}, [%4];"
                 : "=r"(r[0]), "=r"(r[1]), "=r"(r[2]), "=r"(r[3]) : "r"(addr));
}

__device__ __forceinline__ void mma16816(float* c, const uint32_t* a,
                                         uint32_t b0, uint32_t b1) {
    asm volatile(
        "mma.sync.aligned.m16n8k16.row.col.f32.bf16.bf16.f32 "
        "{%0,%1,%2,%3}, {%4,%5,%6,%7}, {%8,%9}, {%0,%1,%2,%3};"
        : "+f"(c[0]), "+f"(c[1]), "+f"(c[2]), "+f"(c[3])
        : "r"(a[0]), "r"(a[1]), "r"(a[2]), "r"(a[3]), "r"(b0), "r"(b1));
}

// Build exclusive scan of the NCHUNK chunk totals into smem (warp 0), sync.
__device__ __forceinline__ void build_ssum(int* ssum) {
    int tid = threadIdx.x;
    if (tid < 32) {
        int b = tid * 4;
        int a0 = (b + 0 < NCHUNK) ? g_sums[b + 0] : 0;
        int a1 = (b + 1 < NCHUNK) ? g_sums[b + 1] : 0;
        int a2 = (b + 2 < NCHUNK) ? g_sums[b + 2] : 0;
        int a3 = (b + 3 < NCHUNK) ? g_sums[b + 3] : 0;
        int t = a0 + a1 + a2 + a3;
        int v = t;
#pragma unroll
        for (int d = 1; d < 32; d <<= 1) {
            int u = __shfl_up_sync(0xffffffffu, v, d);
            if (tid >= d) v += u;
        }
        int excl = v - t;
        if (b + 0 < NCHUNK) ssum[b + 0] = excl;
        if (b + 1 < NCHUNK) ssum[b + 1] = excl + a0;
        if (b + 2 < NCHUNK) ssum[b + 2] = excl + a0 + a1;
        if (b + 3 < NCHUNK) ssum[b + 3] = excl + a0 + a1 + a2;
    }
    __syncthreads();
}

// ---------------------------------------------------------------------------
// x -> bf16 conversion (8 elems/thread), fused with pool/cnt zeroing.
// ---------------------------------------------------------------------------
__global__ void __launch_bounds__(256) k_cvt(const float* __restrict__ x,
                                             __nv_bfloat16* __restrict__ xb) {
    int i = blockIdx.x * blockDim.x + threadIdx.x;
    if (i < N_NODES * D / 8) {
        float4 a = __ldg((const float4*)x + (size_t)i * 2);
        float4 b = __ldg((const float4*)x + (size_t)i * 2 + 1);
        uint4 o;
        o.x = pack2(a.x, a.y);
        o.y = pack2(a.z, a.w);
        o.z = pack2(b.x, b.y);
        o.w = pack2(b.z, b.w);
        ((uint4*)xb)[i] = o;
    }
    if (i < N_GRAPHS * D) g_pool[i] = 0.f;
    if (i < N_GRAPHS) g_cnt[i] = 0.f;
}

// ---------------------------------------------------------------------------
// Init: zero deg / cur
// ---------------------------------------------------------------------------
__global__ void k_init() {
    int i = blockIdx.x * blockDim.x + threadIdx.x;
    if (i < N_NODES) { g_deg[i] = 0; g_cur[i] = 0; }
}

// ---------------------------------------------------------------------------
// Degree histogram over explicit edges
// ---------------------------------------------------------------------------
__global__ void k_deg(const int* __restrict__ dst, int E) {
    int e = blockIdx.x * blockDim.x + threadIdx.x;
    if (e < E) atomicAdd(&g_deg[__ldg(&dst[e])], 1);
}

// ---------------------------------------------------------------------------
// Chunk-local exclusive scan of g_deg -> g_off, fused with dis = rsqrt(deg+1).
// ---------------------------------------------------------------------------
__global__ void __launch_bounds__(256) k_scan1(int n) {
    __shared__ int wsum[8];
    int tid = threadIdx.x, lane = tid & 31, wid = tid >> 5;
    int base = blockIdx.x * 1024 + tid * 4;
    int a0 = (base + 0 < n) ? g_deg[base + 0] : 0;
    int a1 = (base + 1 < n) ? g_deg[base + 1] : 0;
    int a2 = (base + 2 < n) ? g_deg[base + 2] : 0;
    int a3 = (base + 3 < n) ? g_deg[base + 3] : 0;
    if (base + 0 < n) g_dis[base + 0] = rsqrtf((float)a0 + 1.0f);
    if (base + 1 < n) g_dis[base + 1] = rsqrtf((float)a1 + 1.0f);
    if (base + 2 < n) g_dis[base + 2] = rsqrtf((float)a2 + 1.0f);
    if (base + 3 < n) g_dis[base + 3] = rsqrtf((float)a3 + 1.0f);
    int t = a0 + a1 + a2 + a3;
    int v = t;
#pragma unroll
    for (int d = 1; d < 32; d <<= 1) {
        int u = __shfl_up_sync(0xffffffffu, v, d);
        if (lane >= d) v += u;
    }
    if (lane == 31) wsum[wid] = v;
    __syncthreads();
    if (wid == 0) {
        int s = (lane < 8) ? wsum[lane] : 0;
#pragma unroll
        for (int d = 1; d < 8; d <<= 1) {
            int u = __shfl_up_sync(0xffffffffu, s, d);
            if (lane >= d) s += u;
        }
        if (lane < 8) wsum[lane] = s;
    }
    __syncthreads();
    int warpExcl = wid ? wsum[wid - 1] : 0;
    int excl = warpExcl + v - t;
    if (base + 0 < n) g_off[base + 0] = excl;
    if (base + 1 < n) g_off[base + 1] = excl + a0;
    if (base + 2 < n) g_off[base + 2] = excl + a0 + a1;
    if (base + 3 < n) g_off[base + 3] = excl + a0 + a1 + a2;
    if (tid == 255) g_sums[blockIdx.x] = warpExcl + v;
}

// ---------------------------------------------------------------------------
// CSR fill: pos = global_off(dst) + cursor bump; csr[pos] = src
// ---------------------------------------------------------------------------
__global__ void __launch_bounds__(256) k_fill(
    const int* __restrict__ src, const int* __restrict__ dst, int E)
{
    __shared__ int ssum[NCHUNK];
    build_ssum(ssum);
    int e = blockIdx.x * blockDim.x + threadIdx.x;
    if (e < E) {
        int d = __ldg(&dst[e]);
        int s = __ldg(&src[e]);
        int pos = g_off[d] + ssum[d >> 10] + atomicAdd(&g_cur[d], 1);
        g_csr[pos] = s;
    }
}

// ---------------------------------------------------------------------------
// bf16 tensor-core GEMM, cp.async double-buffered A staging:
// C[r] = e4m3( dis[r] * (A[r] @ W) ).  A[N,128] bf16, W[128,128] fp32.
// 256 threads (8 warps), BM=128, BN=128, BK=32 x 4 chunks.
// Dynamic smem: As[2][128][40] bf16 (20480B) + Ws[128][136] bf16 (34816B).
// ---------------------------------------------------------------------------
#define GEMM_SMEM 55296
__global__ void __launch_bounds__(256, 2) k_gemm(
    const __nv_bfloat16* __restrict__ A, const float* __restrict__ W,
    uint8_t* __restrict__ C, int N)
{
    extern __shared__ __align__(16) char dynsmem[];
    __nv_bfloat16* AsB = (__nv_bfloat16*)dynsmem;              // [2][128][40]
    __nv_bfloat16* WsB = (__nv_bfloat16*)(dynsmem + 20480);    // [128][136]
#define AS(b, r, c) AsB[((b) * 128 + (r)) * 40 + (c)]
#define WS(r, c)    WsB[(r) * 136 + (c)]

    const int tid  = threadIdx.x;
    const int lane = tid & 31;
    const int warp = tid >> 5;       // 0..7
    const int gid  = lane >> 2;      // 0..7
    const int tig  = lane & 3;       // 0..3
    const int r0   = blockIdx.x * 128;
    const int wrow = warp * 16;

    // A chunk staging via cp.async (512 x 16B per chunk)
    auto stageA = [&](int c, int buf) {
#pragma unroll
        for (int i = 0; i < 2; i++) {
            int f   = tid + i * 256;
            int row = f >> 2;
            int c8  = (f & 3) * 8;
            int r   = r0 + row;
            cpa16(s2u(&AS(buf, row, c8)),
                  A + (size_t)r * 128 + c * 32 + c8, r < N);
        }
        asm volatile("cp.async.commit_group;");
    };

    stageA(0, 0);
    stageA(1, 1);

    // Stage full W (bf16): 128x128, 16 float4 per thread.
#pragma unroll
    for (int i = 0; i < 16; i++) {
        int f   = tid + i * 256;
        int row = f >> 5;
        int c4  = (f & 31) * 4;
        float4 v = *(const float4*)&W[(size_t)row * 128 + c4];
        uint2 p;
        p.x = pack2(v.x, v.y);
        p.y = pack2(v.z, v.w);
        *(uint2*)&WS(row, c4) = p;
    }

    float acc[16][4];
#pragma unroll
    for (int j = 0; j < 16; j++)
#pragma unroll
        for (int i = 0; i < 4; i++) acc[j][i] = 0.f;

    const int l8  = lane & 7;
    const int grp = lane >> 3;       // 0..3

#pragma unroll
    for (int c = 0; c < 4; c++) {
        if (c < 3) asm volatile("cp.async.wait_group 1;");
        else       asm volatile("cp.async.wait_group 0;");
        __syncthreads();

        const int cb = c & 1;
        uint32_t a[2][4];
        {
            int arow = wrow + (grp & 1) * 8 + l8;
            int acol = (grp >> 1) * 8;
            ldsm_x4(a[0], s2u(&AS(cb, arow, acol)));
            ldsm_x4(a[1], s2u(&AS(cb, arow, 16 + acol)));
        }
        int brow = c * 32 + lane;
#pragma unroll
        for (int j = 0; j < 16; j++) {
            uint32_t b[4];
            ldsm_x4_t(b, s2u(&WS(brow, j * 8)));
            mma16816(acc[j], a[0], b[0], b[1]);
            mma16816(acc[j], a[1], b[2], b[3]);
        }
        __syncthreads();
        if (c < 2) stageA(c + 2, cb);
    }

    // epilogue: scale by dis, convert to e4m3, store fp8x2
    int row0 = r0 + wrow + gid;
    int row1 = row0 + 8;
    float s0 = (row0 < N) ? __ldg(&g_dis[row0]) : 0.f;
    float s1 = (row1 < N) ? __ldg(&g_dis[row1]) : 0.f;
#pragma unroll
    for (int j = 0; j < 16; j++) {
        int c = j * 8 + 2 * tig;
        if (row0 < N)
            *(unsigned short*)&C[(size_t)row0 * 128 + c] =
                pack_fp8x2(acc[j][0] * s0, acc[j][1] * s0);
        if (row1 < N)
            *(unsigned short*)&C[(size_t)row1 * 128 + c] =
                pack_fp8x2(acc[j][2] * s1, acc[j][3] * s1);
    }
#undef AS
#undef WS
}

// ---------------------------------------------------------------------------
// CSR aggregation over fp8 rows, warp per dst node, fp32 accumulate,
// fused self-loop + bias + relu. Gather unrolled 8-wide.
// POOL=true: reduce the row into g_pool/g_cnt instead of writing it.
// ---------------------------------------------------------------------------
template <bool POOL>
__global__ void __launch_bounds__(256) k_agg(
    const uint8_t* __restrict__ hs, const float* __restrict__ bias,
    const int* __restrict__ batch, __nv_bfloat16* __restrict__ out, int N)
{
    __shared__ int ssum[NCHUNK];
    build_ssum(ssum);

    int t    = blockIdx.x * blockDim.x + threadIdx.x;
    int w    = t >> 5;
    int lane = t & 31;
    if (w >= N) return;

    int beg = g_off[w] + ssum[w >> 10];
    int end = beg + g_deg[w];

    float4 acc = ld_row_fp8(hs + (size_t)w * 128, lane);   // self term

    for (int e0 = beg; e0 < end; e0 += 32) {
        int ecnt = min(32, end - e0);
        int idx  = (lane < ecnt) ? __ldg(&g_csr[e0 + lane]) : 0;
        int j = 0;
        for (; j + 8 <= ecnt; j += 8) {
            int s0 = __shfl_sync(0xffffffffu, idx, j);
            int s1 = __shfl_sync(0xffffffffu, idx, j + 1);
            int s2 = __shfl_sync(0xffffffffu, idx, j + 2);
            int s3 = __shfl_sync(0xffffffffu, idx, j + 3);
            int s4 = __shfl_sync(0xffffffffu, idx, j + 4);
            int s5 = __shfl_sync(0xffffffffu, idx, j + 5);
            int s6 = __shfl_sync(0xffffffffu, idx, j + 6);
            int s7 = __shfl_sync(0xffffffffu, idx, j + 7);
            uint32_t r0 = __ldg((const uint32_t*)(hs + (size_t)s0 * 128) + lane);
            uint32_t r1 = __ldg((const uint32_t*)(hs + (size_t)s1 * 128) + lane);
            uint32_t r2 = __ldg((const uint32_t*)(hs + (size_t)s2 * 128) + lane);
            uint32_t r3 = __ldg((const uint32_t*)(hs + (size_t)s3 * 128) + lane);
            uint32_t r4 = __ldg((const uint32_t*)(hs + (size_t)s4 * 128) + lane);
            uint32_t r5 = __ldg((const uint32_t*)(hs + (size_t)s5 * 128) + lane);
            uint32_t r6 = __ldg((const uint32_t*)(hs + (size_t)s6 * 128) + lane);
            uint32_t r7 = __ldg((const uint32_t*)(hs + (size_t)s7 * 128) + lane);
            float4 v0 = fp8x4_to_float4(r0);
            float4 v1 = fp8x4_to_float4(r1);
            float4 v2 = fp8x4_to_float4(r2);
            float4 v3 = fp8x4_to_float4(r3);
            float4 v4 = fp8x4_to_float4(r4);
            float4 v5 = fp8x4_to_float4(r5);
            float4 v6 = fp8x4_to_float4(r6);
            float4 v7 = fp8x4_to_float4(r7);
            acc.x += ((v0.x + v1.x) + (v2.x + v3.x)) + ((v4.x + v5.x) + (v6.x + v7.x));
            acc.y += ((v0.y + v1.y) + (v2.y + v3.y)) + ((v4.y + v5.y) + (v6.y + v7.y));
            acc.z += ((v0.z + v1.z) + (v2.z + v3.z)) + ((v4.z + v5.z) + (v6.z + v7.z));
            acc.w += ((v0.w + v1.w) + (v2.w + v3.w)) + ((v4.w + v5.w) + (v6.w + v7.w));
        }
        for (; j < ecnt; j++) {
            int s = __shfl_sync(0xffffffffu, idx, j);
            float4 v = ld_row_fp8(hs + (size_t)s * 128, lane);
            acc.x += v.x; acc.y += v.y; acc.z += v.z; acc.w += v.w;
        }
    }

    float dd  = __ldg(&g_dis[w]);
    float4 bv = __ldg((const float4*)bias + lane);
    float4 o;
    o.x = fmaxf(acc.x * dd + bv.x, 0.f);
    o.y = fmaxf(acc.y * dd + bv.y, 0.f);
    o.z = fmaxf(acc.z * dd + bv.z, 0.f);
    o.w = fmaxf(acc.w * dd + bv.w, 0.f);

    if (POOL) {
        int g = __ldg(&batch[w]);
        float* p = &g_pool[(size_t)g * 128 + lane * 4];
        asm volatile("red.global.add.v4.f32 [%0], {%1,%2,%3,%4};"
                     :: "l"(p), "f"(o.x), "f"(o.y), "f"(o.z), "f"(o.w)
                     : "memory");
        if (lane == 0) atomicAdd(&g_cnt[g], 1.0f);
    } else {
        uint2 pv;
        pv.x = pack2(o.x, o.y);
        pv.y = pack2(o.z, o.w);
        ((uint2*)(out + (size_t)w * 128))[lane] = pv;
    }
}

// ---------------------------------------------------------------------------
// Head: per graph mean, fc1+relu, fc2, log_softmax(2).
// ---------------------------------------------------------------------------
__global__ void __launch_bounds__(128) k_head(
    const float* __restrict__ fc1w, const float* __restrict__ fc1b,
    const float* __restrict__ fc2w, const float* __restrict__ fc2b,
    float* __restrict__ out)
{
    __shared__ float p[128];
    __shared__ float a[128];
    __shared__ float lg[2];
    int g = blockIdx.x;
    int c = threadIdx.x;

    float invc = 1.0f / fmaxf(g_cnt[g], 1.0f);
    p[c] = g_pool[(size_t)g * 128 + c] * invc;
    __syncthreads();

    float s = fc1b[c];
#pragma unroll 8
    for (int k = 0; k < 128; k++) s += p[k] * fc1w[(size_t)k * 128 + c];
    a[c] = fmaxf(s, 0.f);
    __syncthreads();

    if (c < 2) {
        float s2 = fc2b[c];
#pragma unroll 8
        for (int k = 0; k < 128; k++) s2 += a[k] * fc2w[k * 2 + c];
        lg[c] = s2;
    }
    __syncthreads();

    if (c < 2) {
        float m   = fmaxf(lg[0], lg[1]);
        float lse = m + logf(expf(lg[0] - m) + expf(lg[1] - m));
        out[g * 2 + c] = lg[c] - lse;
    }
}

// ---------------------------------------------------------------------------
// Side stream + events (created pre-main; launch sequence is call-invariant)
// ---------------------------------------------------------------------------
namespace {
struct SideStream {
    cudaStream_t s2;
    cudaEvent_t evA, evB, evC, evD;
    SideStream() {
        cudaStreamCreateWithFlags(&s2, cudaStreamNonBlocking);
        cudaEventCreateWithFlags(&evA, cudaEventDisableTiming);
        cudaEventCreateWithFlags(&evB, cudaEventDisableTiming);
        cudaEventCreateWithFlags(&evC, cudaEventDisableTiming);
        cudaEventCreateWithFlags(&evD, cudaEventDisableTiming);
    }
};
SideStream g_ss;
}

// ---------------------------------------------------------------------------
// Launch
// ---------------------------------------------------------------------------
extern "C" void kernel_launch(void* const* d_in, const int* in_sizes, int n_in,
                              void* d_out, int out_size)
{
    const float* x     = (const float*)d_in[0];
    const int*   ei    = (const int*)  d_in[1];
    const int*   batch = (const int*)  d_in[2];
    const float* W1    = (const float*)d_in[3];
    const float* b1    = (const float*)d_in[4];
    const float* W2    = (const float*)d_in[5];
    const float* b2    = (const float*)d_in[6];
    const float* fc1w  = (const float*)d_in[7];
    const float* fc1b  = (const float*)d_in[8];
    const float* fc2w  = (const float*)d_in[9];
    const float* fc2b  = (const float*)d_in[10];

    const int* src = ei;
    const int* dst = ei + N_EDGES;

    uint8_t* pH;
    __nv_bfloat16 *pAct, *pXb;
    cudaGetSymbolAddress((void**)&pH,   g_hs);
    cudaGetSymbolAddress((void**)&pAct, g_actb);
    cudaGetSymbolAddress((void**)&pXb,  g_xb);

    cudaFuncSetAttribute(k_gemm, cudaFuncAttributeMaxDynamicSharedMemorySize,
                         GEMM_SMEM);

    const int TB = 256;
    const int edge_blocks = (N_EDGES + TB - 1) / TB;
    const int gemm_blocks = (N_NODES + 127) / 128;
    const int agg_blocks  = (N_NODES * 32 + TB - 1) / TB;
    const int cvt_blocks  = (N_NODES * D / 8 + TB - 1) / TB;

    // fork: x->bf16 conversion on side stream (overlaps init/deg/scan1)
    cudaEventRecord(g_ss.evA, 0);
    cudaStreamWaitEvent(g_ss.s2, g_ss.evA, 0);
    k_cvt<<<cvt_blocks, TB, 0, g_ss.s2>>>(x, pXb);
    cudaEventRecord(g_ss.evC, g_ss.s2);

    // setup chain on main stream
    k_init<<<(N_NODES + TB - 1) / TB, TB>>>();
    k_deg<<<edge_blocks, TB>>>(dst, N_EDGES);
    k_scan1<<<NCHUNK, TB>>>(N_NODES);

    // fork: fill on side stream after scan1
    cudaEventRecord(g_ss.evD, 0);
    cudaStreamWaitEvent(g_ss.s2, g_ss.evD, 0);
    k_fill<<<edge_blocks, TB, 0, g_ss.s2>>>(src, dst, N_EDGES);
    cudaEventRecord(g_ss.evB, g_ss.s2);

    // gemm1 on main (needs cvt + scan1)
    cudaStreamWaitEvent(0, g_ss.evC, 0);
    k_gemm<<<gemm_blocks, TB, GEMM_SMEM>>>(pXb, W1, pH, N_NODES);

    // join fill, then the rest
    cudaStreamWaitEvent(0, g_ss.evB, 0);
    k_agg<false><<<agg_blocks, TB>>>(pH, b1, batch, pAct, N_NODES);
    k_gemm<<<gemm_blocks, TB, GEMM_SMEM>>>(pAct, W2, pH, N_NODES);
    k_agg<true><<<agg_blocks, TB>>>(pH, b2, batch, nullptr, N_NODES);
    k_head<<<N_GRAPHS, 128>>>(fc1w, fc1b, fc2w, fc2b, (float*)d_out);
}